// round 13
// baseline (speedup 1.0000x reference)
#include <cuda_runtime.h>
#include <cuda_fp16.h>
#include <math.h>
#include <stdint.h>

#define T_TOK   32768
#define H_DIM   256
#define F_DIM   512
#define E_NUM   16
#define ROWS_PAD 67584            // 2*T + E*128 (worst-case segment padding)
#define MAXT    (ROWS_PAD / 128)  // 528 m-tiles

// ---------------- scratch (ALL accessed via device symbols ONLY) ----------------
__device__ int    g_counts[E_NUM];
__device__ int    g_cursor[E_NUM];
__device__ int    g_poff[E_NUM + 1];
__device__ int    g_eid[T_TOK * 2];
__device__ float  g_gw[T_TOK * 2];
__device__ int    g_rowtok[ROWS_PAD];
__device__ int    g_tokrow[T_TOK * 2];
__device__ __half g_xh[(size_t)T_TOK * H_DIM];            // x (fp16)
__device__ __half g_h[(size_t)ROWS_PAD * F_DIM];          // hidden (fp16)
__device__ float  g_eout[(size_t)ROWS_PAD * H_DIM];       // expert out (fp32)
__device__ __half g_w1h[(size_t)E_NUM * H_DIM * F_DIM];   // [E][K=H][N=F] fp16
__device__ __half g_w2h[(size_t)E_NUM * F_DIM * H_DIM];   // [E][K=F][N=H] fp16

// ---------------- init ----------------
__global__ void k_init() {
    int i = blockIdx.x * blockDim.x + threadIdx.x;
    if (i < ROWS_PAD) g_rowtok[i] = -1;
    if (i < E_NUM) { g_counts[i] = 0; g_cursor[i] = 0; }
}

// ---------------- fp32 -> fp16 converters (symbol destinations) ----------------
__device__ __forceinline__ uint4 cvt8(const float* __restrict__ src, int i) {
    const float4* s = (const float4*)src + i * 2;
    float4 u0 = s[0], u1 = s[1];
    __half2 h0 = __floats2half2_rn(u0.x, u0.y);
    __half2 h1 = __floats2half2_rn(u0.z, u0.w);
    __half2 h2 = __floats2half2_rn(u1.x, u1.y);
    __half2 h3 = __floats2half2_rn(u1.z, u1.w);
    uint4 o;
    o.x = reinterpret_cast<uint32_t&>(h0);
    o.y = reinterpret_cast<uint32_t&>(h1);
    o.z = reinterpret_cast<uint32_t&>(h2);
    o.w = reinterpret_cast<uint32_t&>(h3);
    return o;
}
__global__ void k_cvt_w1(const float* __restrict__ src) {
    int i = blockIdx.x * blockDim.x + threadIdx.x;
    ((uint4*)g_w1h)[i] = cvt8(src, i);
}
__global__ void k_cvt_w2(const float* __restrict__ src) {
    int i = blockIdx.x * blockDim.x + threadIdx.x;
    ((uint4*)g_w2h)[i] = cvt8(src, i);
}

// ---------------- gating (also emits x in fp16 to g_xh) ----------------
__global__ void k_gate(const float* __restrict__ x, const float* __restrict__ gw,
                       const float* __restrict__ gb) {
    __shared__ float sgw[H_DIM * 17];
    int tid = threadIdx.x;
    for (int i = tid; i < H_DIM * E_NUM; i += 256) {
        int h = i >> 4, e = i & 15;
        sgw[h * 17 + e] = gw[i];
    }
    __syncthreads();
    int warp = tid >> 5, lane = tid & 31;
    int t = blockIdx.x * 8 + warp;
    float acc[E_NUM];
#pragma unroll
    for (int e = 0; e < E_NUM; e++) acc[e] = 0.f;
    const float* xr = x + (size_t)t * H_DIM;
    __half* xhw = g_xh + (size_t)t * H_DIM;
#pragma unroll
    for (int c = 0; c < H_DIM / 32; c++) {
        int h = c * 32 + lane;
        float xv = xr[h];
        xhw[h] = __float2half(xv);
#pragma unroll
        for (int e = 0; e < E_NUM; e++) acc[e] += xv * sgw[h * 17 + e];
    }
#pragma unroll
    for (int e = 0; e < E_NUM; e++) {
        float v = acc[e];
        v += __shfl_down_sync(0xffffffffu, v, 16);
        v += __shfl_down_sync(0xffffffffu, v, 8);
        v += __shfl_down_sync(0xffffffffu, v, 4);
        v += __shfl_down_sync(0xffffffffu, v, 2);
        v += __shfl_down_sync(0xffffffffu, v, 1);
        acc[e] = v;
    }
    if (lane == 0) {
        float logit[E_NUM];
#pragma unroll
        for (int e = 0; e < E_NUM; e++) logit[e] = acc[e] + gb[e];
        int i0 = 0; float m0 = logit[0];
#pragma unroll
        for (int e = 1; e < E_NUM; e++) if (logit[e] > m0) { m0 = logit[e]; i0 = e; }
        int i1 = -1; float m1 = -3.0e38f;
#pragma unroll
        for (int e = 0; e < E_NUM; e++)
            if (e != i0 && logit[e] > m1) { m1 = logit[e]; i1 = e; }
        float z = expf(m1 - m0);
        float w0 = 1.f / (1.f + z);
        float w1 = z * w0;
        g_eid[t * 2 + 0] = i0; g_eid[t * 2 + 1] = i1;
        g_gw[t * 2 + 0] = w0;  g_gw[t * 2 + 1] = w1;
        atomicAdd(&g_counts[i0], 1);
        atomicAdd(&g_counts[i1], 1);
    }
}

__global__ void k_scan() {
    if (threadIdx.x == 0) {
        int off = 0;
        g_poff[0] = 0;
        for (int e = 0; e < E_NUM; e++) {
            off += (g_counts[e] + 127) & ~127;
            g_poff[e + 1] = off;
        }
    }
}

__global__ void k_scatter() {
    int t = blockIdx.x * blockDim.x + threadIdx.x;
    if (t >= T_TOK) return;
#pragma unroll
    for (int k = 0; k < 2; k++) {
        int e = g_eid[t * 2 + k];
        int pos = atomicAdd(&g_cursor[e], 1);
        int row = g_poff[e] + pos;
        g_rowtok[row] = t;
        g_tokrow[t * 2 + k] = row;
    }
}

// ---------------- grouped GEMM: all-fp16, HFMA2, splat-A SMEM, k16, dbl-buffered ----------------
template <int KDIM, int NDIM, bool GATHER, bool RELU>
__global__ __launch_bounds__(256, 2)
void k_gemm(const float* __restrict__ bias) {
    int r0 = blockIdx.x * 128;
    if (r0 >= g_poff[E_NUM]) return;
    int e = 0;
#pragma unroll
    for (int i = 1; i < E_NUM; i++) if (r0 >= g_poff[i]) e = i;

    const __half* Wb = (GATHER ? g_w1h : g_w2h) + (size_t)e * KDIM * NDIM;
    int n0 = blockIdx.y * 128;
    int tid = threadIdx.x;

    __shared__ __half2 As2[2][16][128];   // splat: both lanes = a value
    __shared__ __half  Bs[2][16][128];

    int arow = tid >> 1;
    int acol = (tid & 1) * 8;       // 8 halves = 16 B per thread
    int brow = tid >> 4;            // 0..15
    int bcol = (tid & 15) * 8;      // 8 halves = 16 B per thread

    const __half* Aptr;
    if (GATHER) {
        int tok = g_rowtok[r0 + arow];
        Aptr = (tok >= 0) ? (g_xh + (size_t)tok * KDIM + acol) : nullptr;
    } else {
        Aptr = g_h + (size_t)(r0 + arow) * KDIM + acol;
    }
    const __half* Wrow = Wb + (size_t)brow * NDIM + n0 + bcol;

    int ty = tid >> 4, tx = tid & 15;
    float accf[8][8];
#pragma unroll
    for (int i = 0; i < 8; i++)
#pragma unroll
        for (int j = 0; j < 8; j++) accf[i][j] = 0.f;

    __half2 acc2[8][4];
#pragma unroll
    for (int i = 0; i < 8; i++)
#pragma unroll
        for (int j = 0; j < 4; j++) acc2[i][j] = __float2half2_rn(0.f);

    constexpr int CHUNKS = KDIM / 16;

    // prologue: chunk 0 into buffer 0
    {
        uint4 avr = make_uint4(0u, 0u, 0u, 0u);
        if (!GATHER || Aptr) avr = *(const uint4*)(Aptr);
        const __half* hv = (const __half*)&avr;
#pragma unroll
        for (int i = 0; i < 8; i++) As2[0][acol + i][arow] = __half2half2(hv[i]);
        *(uint4*)&Bs[0][brow][bcol] = *(const uint4*)(Wrow);
    }
    __syncthreads();

    for (int c = 0; c < CHUNKS; c++) {
        const int b = c & 1;
        uint4 avr, bwr;
        const bool more = (c + 1 < CHUNKS);
        if (more) {
            avr = make_uint4(0u, 0u, 0u, 0u);
            if (!GATHER || Aptr) avr = *(const uint4*)(Aptr + (c + 1) * 16);
            bwr = *(const uint4*)(Wrow + (size_t)(c + 1) * 16 * NDIM);
        }

#pragma unroll
        for (int k = 0; k < 16; k++) {
            __half2 a2[8];
            *(uint4*)&a2[0] = *(const uint4*)&As2[b][k][ty * 8];
            *(uint4*)&a2[4] = *(const uint4*)&As2[b][k][ty * 8 + 4];
            __half2 b2[4];
            {
                uint4 bp = *(const uint4*)&Bs[b][k][tx * 8];
                b2[0] = reinterpret_cast<__half2&>(bp.x);
                b2[1] = reinterpret_cast<__half2&>(bp.y);
                b2[2] = reinterpret_cast<__half2&>(bp.z);
                b2[3] = reinterpret_cast<__half2&>(bp.w);
            }
#pragma unroll
            for (int i = 0; i < 8; i++)
#pragma unroll
                for (int j = 0; j < 4; j++)
                    acc2[i][j] = __hfma2(a2[i], b2[j], acc2[i][j]);
        }

        if ((c & 1) == 1) {   // flush fp16 window -> fp32 every 32 k-steps
#pragma unroll
            for (int i = 0; i < 8; i++)
#pragma unroll
                for (int j = 0; j < 4; j++) {
                    float2 f = __half22float2(acc2[i][j]);
                    accf[i][j * 2 + 0] += f.x;
                    accf[i][j * 2 + 1] += f.y;
                    acc2[i][j] = __float2half2_rn(0.f);
                }
        }

        if (more) {
            const int nb = 1 - b;
            const __half* hv = (const __half*)&avr;
#pragma unroll
            for (int i = 0; i < 8; i++) As2[nb][acol + i][arow] = __half2half2(hv[i]);
            *(uint4*)&Bs[nb][brow][bcol] = bwr;
            __syncthreads();
        }
    }

    float bv[8];
#pragma unroll
    for (int j = 0; j < 8; j++) bv[j] = bias[(size_t)e * NDIM + n0 + tx * 8 + j];

#pragma unroll
    for (int i = 0; i < 8; i++) {
        int r = r0 + ty * 8 + i;
        float o[8];
#pragma unroll
        for (int j = 0; j < 8; j++) {
            float v = accf[i][j] + bv[j];
            if (RELU) v = fmaxf(v, 0.f);
            o[j] = v;
        }
        if (RELU) {
            __half2 h0 = __floats2half2_rn(o[0], o[1]);
            __half2 h1 = __floats2half2_rn(o[2], o[3]);
            __half2 h2 = __floats2half2_rn(o[4], o[5]);
            __half2 h3 = __floats2half2_rn(o[6], o[7]);
            uint4 pk;
            pk.x = reinterpret_cast<uint32_t&>(h0);
            pk.y = reinterpret_cast<uint32_t&>(h1);
            pk.z = reinterpret_cast<uint32_t&>(h2);
            pk.w = reinterpret_cast<uint32_t&>(h3);
            *(uint4*)(g_h + (size_t)r * NDIM + n0 + tx * 8) = pk;
        } else {
            float* cp = g_eout + (size_t)r * NDIM + n0 + tx * 8;
            *(float4*)&cp[0] = *(float4*)&o[0];
            *(float4*)&cp[4] = *(float4*)&o[4];
        }
    }
}

// ---------------- combine + residual + LayerNorm ----------------
__global__ void k_combine_ln(const float* __restrict__ x,
                             const float* __restrict__ gamma,
                             const float* __restrict__ beta,
                             float* __restrict__ out) {
    int warp = threadIdx.x >> 5, lane = threadIdx.x & 31;
    int t = blockIdx.x * 8 + warp;
    int row0 = g_tokrow[t * 2 + 0];
    int row1 = g_tokrow[t * 2 + 1];
    float w0 = g_gw[t * 2 + 0];
    float w1 = g_gw[t * 2 + 1];
    const float* xr = x + (size_t)t * H_DIM;
    const float* o0 = g_eout + (size_t)row0 * H_DIM;
    const float* o1 = g_eout + (size_t)row1 * H_DIM;

    float v[8];
    float s = 0.f, sq = 0.f;
#pragma unroll
    for (int j = 0; j < 8; j++) {
        int h = j * 32 + lane;
        float y = xr[h] + w0 * o0[h] + w1 * o1[h];
        v[j] = y;
        s += y;
        sq += y * y;
    }
#pragma unroll
    for (int off = 16; off > 0; off >>= 1) {
        s  += __shfl_xor_sync(0xffffffffu, s, off);
        sq += __shfl_xor_sync(0xffffffffu, sq, off);
    }
    float mu = s * (1.f / H_DIM);
    float var = sq * (1.f / H_DIM) - mu * mu;
    float rs = rsqrtf(var + 1e-5f);
    float* outr = out + (size_t)t * H_DIM;
#pragma unroll
    for (int j = 0; j < 8; j++) {
        int h = j * 32 + lane;
        outr[h] = (v[j] - mu) * rs * gamma[h] + beta[h];
    }
}

// ---------------- launch ----------------
extern "C" void kernel_launch(void* const* d_in, const int* in_sizes, int n_in,
                              void* d_out, int out_size) {
    const float* x      = (const float*)d_in[0];
    const float* gate_w = (const float*)d_in[1];
    const float* gate_b = (const float*)d_in[2];
    const float* w1     = (const float*)d_in[3];
    const float* b1     = (const float*)d_in[4];
    const float* w2     = (const float*)d_in[5];
    const float* b2     = (const float*)d_in[6];
    const float* gamma  = (const float*)d_in[7];
    const float* beta   = (const float*)d_in[8];
    float* out = (float*)d_out;

    k_init<<<(ROWS_PAD + 255) / 256, 256>>>();
    k_cvt_w1<<<E_NUM * H_DIM * F_DIM / 8 / 256, 256>>>(w1);
    k_cvt_w2<<<E_NUM * F_DIM * H_DIM / 8 / 256, 256>>>(w2);
    k_gate<<<T_TOK / 8, 256>>>(x, gate_w, gate_b);
    k_scan<<<1, 32>>>();
    k_scatter<<<T_TOK / 256, 256>>>();
    k_gemm<H_DIM, F_DIM, true,  true ><<<dim3(MAXT, F_DIM / 128), 256>>>(b1);
    k_gemm<F_DIM, H_DIM, false, false><<<dim3(MAXT, H_DIM / 128), 256>>>(b2);
    k_combine_ln<<<T_TOK / 8, 256>>>(x, gamma, beta, out);
}

// round 14
// speedup vs baseline: 1.0393x; 1.0393x over previous
#include <cuda_runtime.h>
#include <cuda_fp16.h>
#include <math.h>
#include <stdint.h>

#define T_TOK   32768
#define H_DIM   256
#define F_DIM   512
#define E_NUM   16
#define ROWS_PAD 67584            // 2*T + E*128 (worst-case segment padding)
#define MAXT    (ROWS_PAD / 128)  // 528 m-tiles

// ---------------- scratch (ALL accessed via device symbols ONLY) ----------------
__device__ int    g_counts[E_NUM];
__device__ int    g_cursor[E_NUM];
__device__ int    g_poff[E_NUM + 1];
__device__ int    g_eid[T_TOK * 2];
__device__ float  g_gw[T_TOK * 2];
__device__ int    g_rowtok[ROWS_PAD];
__device__ int    g_tokrow[T_TOK * 2];
__device__ __half g_xh[(size_t)T_TOK * H_DIM];            // x (fp16)
__device__ __half g_h[(size_t)ROWS_PAD * F_DIM];          // hidden (fp16)
__device__ float  g_eout[(size_t)ROWS_PAD * H_DIM];       // expert out (fp32)
__device__ __half g_w1h[(size_t)E_NUM * H_DIM * F_DIM];   // [E][K=H][N=F] fp16
__device__ __half g_w2h[(size_t)E_NUM * F_DIM * H_DIM];   // [E][K=F][N=H] fp16

// ---------------- init ----------------
__global__ void k_init() {
    int i = blockIdx.x * blockDim.x + threadIdx.x;
    if (i < ROWS_PAD) g_rowtok[i] = -1;
    if (i < E_NUM) { g_counts[i] = 0; g_cursor[i] = 0; }
}

// ---------------- fp32 -> fp16 converters (symbol destinations) ----------------
__device__ __forceinline__ uint4 cvt8(const float* __restrict__ src, int i) {
    const float4* s = (const float4*)src + i * 2;
    float4 u0 = s[0], u1 = s[1];
    __half2 h0 = __floats2half2_rn(u0.x, u0.y);
    __half2 h1 = __floats2half2_rn(u0.z, u0.w);
    __half2 h2 = __floats2half2_rn(u1.x, u1.y);
    __half2 h3 = __floats2half2_rn(u1.z, u1.w);
    uint4 o;
    o.x = reinterpret_cast<uint32_t&>(h0);
    o.y = reinterpret_cast<uint32_t&>(h1);
    o.z = reinterpret_cast<uint32_t&>(h2);
    o.w = reinterpret_cast<uint32_t&>(h3);
    return o;
}
__global__ void k_cvt_w1(const float* __restrict__ src) {
    int i = blockIdx.x * blockDim.x + threadIdx.x;
    ((uint4*)g_w1h)[i] = cvt8(src, i);
}
__global__ void k_cvt_w2(const float* __restrict__ src) {
    int i = blockIdx.x * blockDim.x + threadIdx.x;
    ((uint4*)g_w2h)[i] = cvt8(src, i);
}

// ---------------- gating (vectorized LDS; also emits x in fp16) ----------------
// sgw layout: [H][20] floats (16 payload + 4 pad) -> conflict-free LDS.128.
__global__ void k_gate(const float* __restrict__ x, const float* __restrict__ gw,
                       const float* __restrict__ gb) {
    __shared__ float sgw[H_DIM * 20];
    int tid = threadIdx.x;
    for (int i = tid; i < H_DIM * E_NUM; i += 256) {
        int h = i >> 4, e = i & 15;
        sgw[h * 20 + e] = gw[i];
    }
    __syncthreads();
    int warp = tid >> 5, lane = tid & 31;
    int t = blockIdx.x * 8 + warp;
    float acc[E_NUM];
#pragma unroll
    for (int e = 0; e < E_NUM; e++) acc[e] = 0.f;
    const float* xr = x + (size_t)t * H_DIM;
    __half* xhw = g_xh + (size_t)t * H_DIM;
#pragma unroll
    for (int c = 0; c < H_DIM / 32; c++) {
        int h = c * 32 + lane;
        float xv = xr[h];
        xhw[h] = __float2half(xv);
        const float4* gwr = (const float4*)&sgw[h * 20];
#pragma unroll
        for (int q = 0; q < 4; q++) {
            float4 g4 = gwr[q];
            acc[q * 4 + 0] += xv * g4.x;
            acc[q * 4 + 1] += xv * g4.y;
            acc[q * 4 + 2] += xv * g4.z;
            acc[q * 4 + 3] += xv * g4.w;
        }
    }
#pragma unroll
    for (int e = 0; e < E_NUM; e++) {
        float v = acc[e];
        v += __shfl_down_sync(0xffffffffu, v, 16);
        v += __shfl_down_sync(0xffffffffu, v, 8);
        v += __shfl_down_sync(0xffffffffu, v, 4);
        v += __shfl_down_sync(0xffffffffu, v, 2);
        v += __shfl_down_sync(0xffffffffu, v, 1);
        acc[e] = v;
    }
    if (lane == 0) {
        float logit[E_NUM];
#pragma unroll
        for (int e = 0; e < E_NUM; e++) logit[e] = acc[e] + gb[e];
        int i0 = 0; float m0 = logit[0];
#pragma unroll
        for (int e = 1; e < E_NUM; e++) if (logit[e] > m0) { m0 = logit[e]; i0 = e; }
        int i1 = -1; float m1 = -3.0e38f;
#pragma unroll
        for (int e = 0; e < E_NUM; e++)
            if (e != i0 && logit[e] > m1) { m1 = logit[e]; i1 = e; }
        float z = expf(m1 - m0);
        float w0 = 1.f / (1.f + z);
        float w1 = z * w0;
        g_eid[t * 2 + 0] = i0; g_eid[t * 2 + 1] = i1;
        g_gw[t * 2 + 0] = w0;  g_gw[t * 2 + 1] = w1;
        atomicAdd(&g_counts[i0], 1);
        atomicAdd(&g_counts[i1], 1);
    }
}

__global__ void k_scan() {
    if (threadIdx.x == 0) {
        int off = 0;
        g_poff[0] = 0;
        for (int e = 0; e < E_NUM; e++) {
            off += (g_counts[e] + 127) & ~127;
            g_poff[e + 1] = off;
        }
    }
}

__global__ void k_scatter() {
    int t = blockIdx.x * blockDim.x + threadIdx.x;
    if (t >= T_TOK) return;
#pragma unroll
    for (int k = 0; k < 2; k++) {
        int e = g_eid[t * 2 + k];
        int pos = atomicAdd(&g_cursor[e], 1);
        int row = g_poff[e] + pos;
        g_rowtok[row] = t;
        g_tokrow[t * 2 + k] = row;
    }
}

// ---------------- grouped GEMM: all-fp16, HFMA2, k-depth 16, double-buffered (R12) ----------------
template <int KDIM, int NDIM, bool GATHER, bool RELU>
__global__ __launch_bounds__(256, 2)
void k_gemm(const float* __restrict__ bias) {
    int r0 = blockIdx.x * 128;
    if (r0 >= g_poff[E_NUM]) return;
    int e = 0;
#pragma unroll
    for (int i = 1; i < E_NUM; i++) if (r0 >= g_poff[i]) e = i;

    const __half* Wb = (GATHER ? g_w1h : g_w2h) + (size_t)e * KDIM * NDIM;
    int n0 = blockIdx.y * 128;
    int tid = threadIdx.x;

    __shared__ __half As[2][16][128];
    __shared__ __half Bs[2][16][128];

    int arow = tid >> 1;
    int acol = (tid & 1) * 8;       // 8 halves = 16 B per thread
    int brow = tid >> 4;            // 0..15
    int bcol = (tid & 15) * 8;      // 8 halves = 16 B per thread

    const __half* Aptr;
    if (GATHER) {
        int tok = g_rowtok[r0 + arow];
        Aptr = (tok >= 0) ? (g_xh + (size_t)tok * KDIM + acol) : nullptr;
    } else {
        Aptr = g_h + (size_t)(r0 + arow) * KDIM + acol;
    }
    const __half* Wrow = Wb + (size_t)brow * NDIM + n0 + bcol;

    int ty = tid >> 4, tx = tid & 15;
    float accf[8][8];
#pragma unroll
    for (int i = 0; i < 8; i++)
#pragma unroll
        for (int j = 0; j < 8; j++) accf[i][j] = 0.f;

    __half2 acc2[8][4];
#pragma unroll
    for (int i = 0; i < 8; i++)
#pragma unroll
        for (int j = 0; j < 4; j++) acc2[i][j] = __float2half2_rn(0.f);

    constexpr int CHUNKS = KDIM / 16;

    // prologue: chunk 0 into buffer 0
    {
        uint4 avr = make_uint4(0u, 0u, 0u, 0u);
        if (!GATHER || Aptr) avr = *(const uint4*)(Aptr);
        const __half* hv = (const __half*)&avr;
#pragma unroll
        for (int i = 0; i < 8; i++) As[0][acol + i][arow] = hv[i];
        *(uint4*)&Bs[0][brow][bcol] = *(const uint4*)(Wrow);
    }
    __syncthreads();

    for (int c = 0; c < CHUNKS; c++) {
        const int b = c & 1;
        uint4 avr, bwr;
        const bool more = (c + 1 < CHUNKS);
        if (more) {
            avr = make_uint4(0u, 0u, 0u, 0u);
            if (!GATHER || Aptr) avr = *(const uint4*)(Aptr + (c + 1) * 16);
            bwr = *(const uint4*)(Wrow + (size_t)(c + 1) * 16 * NDIM);
        }

#pragma unroll
        for (int k = 0; k < 16; k++) {
            __half2 a2[8];
            {
                uint4 ap = *(const uint4*)&As[b][k][ty * 8];
                __half2 q0 = reinterpret_cast<__half2&>(ap.x);
                __half2 q1 = reinterpret_cast<__half2&>(ap.y);
                __half2 q2 = reinterpret_cast<__half2&>(ap.z);
                __half2 q3 = reinterpret_cast<__half2&>(ap.w);
                a2[0] = __low2half2(q0);  a2[1] = __high2half2(q0);
                a2[2] = __low2half2(q1);  a2[3] = __high2half2(q1);
                a2[4] = __low2half2(q2);  a2[5] = __high2half2(q2);
                a2[6] = __low2half2(q3);  a2[7] = __high2half2(q3);
            }
            __half2 b2[4];
            {
                uint4 bp = *(const uint4*)&Bs[b][k][tx * 8];
                b2[0] = reinterpret_cast<__half2&>(bp.x);
                b2[1] = reinterpret_cast<__half2&>(bp.y);
                b2[2] = reinterpret_cast<__half2&>(bp.z);
                b2[3] = reinterpret_cast<__half2&>(bp.w);
            }
#pragma unroll
            for (int i = 0; i < 8; i++)
#pragma unroll
                for (int j = 0; j < 4; j++)
                    acc2[i][j] = __hfma2(a2[i], b2[j], acc2[i][j]);
        }

        if ((c & 1) == 1) {   // flush fp16 window -> fp32 every 32 k-steps
#pragma unroll
            for (int i = 0; i < 8; i++)
#pragma unroll
                for (int j = 0; j < 4; j++) {
                    float2 f = __half22float2(acc2[i][j]);
                    accf[i][j * 2 + 0] += f.x;
                    accf[i][j * 2 + 1] += f.y;
                    acc2[i][j] = __float2half2_rn(0.f);
                }
        }

        if (more) {
            const int nb = 1 - b;
            const __half* hv = (const __half*)&avr;
#pragma unroll
            for (int i = 0; i < 8; i++) As[nb][acol + i][arow] = hv[i];
            *(uint4*)&Bs[nb][brow][bcol] = bwr;
            __syncthreads();
        }
    }

    float bv[8];
#pragma unroll
    for (int j = 0; j < 8; j++) bv[j] = bias[(size_t)e * NDIM + n0 + tx * 8 + j];

#pragma unroll
    for (int i = 0; i < 8; i++) {
        int r = r0 + ty * 8 + i;
        float o[8];
#pragma unroll
        for (int j = 0; j < 8; j++) {
            float v = accf[i][j] + bv[j];
            if (RELU) v = fmaxf(v, 0.f);
            o[j] = v;
        }
        if (RELU) {
            __half2 h0 = __floats2half2_rn(o[0], o[1]);
            __half2 h1 = __floats2half2_rn(o[2], o[3]);
            __half2 h2 = __floats2half2_rn(o[4], o[5]);
            __half2 h3 = __floats2half2_rn(o[6], o[7]);
            uint4 pk;
            pk.x = reinterpret_cast<uint32_t&>(h0);
            pk.y = reinterpret_cast<uint32_t&>(h1);
            pk.z = reinterpret_cast<uint32_t&>(h2);
            pk.w = reinterpret_cast<uint32_t&>(h3);
            *(uint4*)(g_h + (size_t)r * NDIM + n0 + tx * 8) = pk;
        } else {
            float* cp = g_eout + (size_t)r * NDIM + n0 + tx * 8;
            *(float4*)&cp[0] = *(float4*)&o[0];
            *(float4*)&cp[4] = *(float4*)&o[4];
        }
    }
}

// ---------------- combine + residual + LayerNorm ----------------
__global__ void k_combine_ln(const float* __restrict__ x,
                             const float* __restrict__ gamma,
                             const float* __restrict__ beta,
                             float* __restrict__ out) {
    int warp = threadIdx.x >> 5, lane = threadIdx.x & 31;
    int t = blockIdx.x * 8 + warp;
    int row0 = g_tokrow[t * 2 + 0];
    int row1 = g_tokrow[t * 2 + 1];
    float w0 = g_gw[t * 2 + 0];
    float w1 = g_gw[t * 2 + 1];
    const float* xr = x + (size_t)t * H_DIM;
    const float* o0 = g_eout + (size_t)row0 * H_DIM;
    const float* o1 = g_eout + (size_t)row1 * H_DIM;

    float v[8];
    float s = 0.f, sq = 0.f;
#pragma unroll
    for (int j = 0; j < 8; j++) {
        int h = j * 32 + lane;
        float y = xr[h] + w0 * o0[h] + w1 * o1[h];
        v[j] = y;
        s += y;
        sq += y * y;
    }
#pragma unroll
    for (int off = 16; off > 0; off >>= 1) {
        s  += __shfl_xor_sync(0xffffffffu, s, off);
        sq += __shfl_xor_sync(0xffffffffu, sq, off);
    }
    float mu = s * (1.f / H_DIM);
    float var = sq * (1.f / H_DIM) - mu * mu;
    float rs = rsqrtf(var + 1e-5f);
    float* outr = out + (size_t)t * H_DIM;
#pragma unroll
    for (int j = 0; j < 8; j++) {
        int h = j * 32 + lane;
        outr[h] = (v[j] - mu) * rs * gamma[h] + beta[h];
    }
}

// ---------------- launch ----------------
extern "C" void kernel_launch(void* const* d_in, const int* in_sizes, int n_in,
                              void* d_out, int out_size) {
    const float* x      = (const float*)d_in[0];
    const float* gate_w = (const float*)d_in[1];
    const float* gate_b = (const float*)d_in[2];
    const float* w1     = (const float*)d_in[3];
    const float* b1     = (const float*)d_in[4];
    const float* w2     = (const float*)d_in[5];
    const float* b2     = (const float*)d_in[6];
    const float* gamma  = (const float*)d_in[7];
    const float* beta   = (const float*)d_in[8];
    float* out = (float*)d_out;

    k_init<<<(ROWS_PAD + 255) / 256, 256>>>();
    k_cvt_w1<<<E_NUM * H_DIM * F_DIM / 8 / 256, 256>>>(w1);
    k_cvt_w2<<<E_NUM * F_DIM * H_DIM / 8 / 256, 256>>>(w2);
    k_gate<<<T_TOK / 8, 256>>>(x, gate_w, gate_b);
    k_scan<<<1, 32>>>();
    k_scatter<<<T_TOK / 256, 256>>>();
    k_gemm<H_DIM, F_DIM, true,  true ><<<dim3(MAXT, F_DIM / 128), 256>>>(b1);
    k_gemm<F_DIM, H_DIM, false, false><<<dim3(MAXT, H_DIM / 128), 256>>>(b2);
    k_combine_ln<<<T_TOK / 8, 256>>>(x, gamma, beta, out);
}

// round 15
// speedup vs baseline: 1.0544x; 1.0145x over previous
#include <cuda_runtime.h>
#include <cuda_fp16.h>
#include <math.h>
#include <stdint.h>

#define T_TOK   32768
#define H_DIM   256
#define F_DIM   512
#define E_NUM   16
#define ROWS_PAD 67584            // 2*T + E*128 (worst-case segment padding)
#define MAXT    (ROWS_PAD / 128)  // 528 m-tiles

// ---------------- scratch (ALL accessed via device symbols ONLY) ----------------
__device__ int    g_counts[E_NUM];
__device__ int    g_cursor[E_NUM];
__device__ int    g_poff[E_NUM + 1];
__device__ int    g_eid[T_TOK * 2];
__device__ float  g_gw[T_TOK * 2];
__device__ int    g_rowtok[ROWS_PAD];
__device__ int    g_tokrow[T_TOK * 2];
__device__ __half g_xh[(size_t)T_TOK * H_DIM];            // x (fp16)
__device__ __half g_h[(size_t)ROWS_PAD * F_DIM];          // hidden (fp16)
__device__ float  g_eout[(size_t)ROWS_PAD * H_DIM];       // expert out (fp32)
__device__ __half g_w1h[(size_t)E_NUM * H_DIM * F_DIM];   // [E][K=H][N=F] fp16
__device__ __half g_w2h[(size_t)E_NUM * F_DIM * H_DIM];   // [E][K=F][N=H] fp16

// ---------------- init ----------------
__global__ void k_init() {
    int i = blockIdx.x * blockDim.x + threadIdx.x;
    if (i < ROWS_PAD) g_rowtok[i] = -1;
    if (i < E_NUM) { g_counts[i] = 0; g_cursor[i] = 0; }
}

// ---------------- fp32 -> fp16 converters (symbol destinations) ----------------
__device__ __forceinline__ uint4 cvt8(const float* __restrict__ src, int i) {
    const float4* s = (const float4*)src + i * 2;
    float4 u0 = s[0], u1 = s[1];
    __half2 h0 = __floats2half2_rn(u0.x, u0.y);
    __half2 h1 = __floats2half2_rn(u0.z, u0.w);
    __half2 h2 = __floats2half2_rn(u1.x, u1.y);
    __half2 h3 = __floats2half2_rn(u1.z, u1.w);
    uint4 o;
    o.x = reinterpret_cast<uint32_t&>(h0);
    o.y = reinterpret_cast<uint32_t&>(h1);
    o.z = reinterpret_cast<uint32_t&>(h2);
    o.w = reinterpret_cast<uint32_t&>(h3);
    return o;
}
__global__ void k_cvt_w1(const float* __restrict__ src) {
    int i = blockIdx.x * blockDim.x + threadIdx.x;
    ((uint4*)g_w1h)[i] = cvt8(src, i);
}
__global__ void k_cvt_w2(const float* __restrict__ src) {
    int i = blockIdx.x * blockDim.x + threadIdx.x;
    ((uint4*)g_w2h)[i] = cvt8(src, i);
}

// ---------------- gating (batched x loads; vectorized LDS; emits x fp16) ----------------
// sgw layout: [H][20] floats (16 payload + 4 pad) -> conflict-free LDS.128.
__global__ void k_gate(const float* __restrict__ x, const float* __restrict__ gw,
                       const float* __restrict__ gb) {
    __shared__ float sgw[H_DIM * 20];
    int tid = threadIdx.x;
    for (int i = tid; i < H_DIM * E_NUM; i += 256) {
        int h = i >> 4, e = i & 15;
        sgw[h * 20 + e] = gw[i];
    }
    __syncthreads();
    int warp = tid >> 5, lane = tid & 31;
    int t = blockIdx.x * 8 + warp;
    const float* xr = x + (size_t)t * H_DIM;
    __half* xhw = g_xh + (size_t)t * H_DIM;

    // batch all 8 loads (MLP=8)
    float xv[8];
#pragma unroll
    for (int c = 0; c < H_DIM / 32; c++) xv[c] = xr[c * 32 + lane];
#pragma unroll
    for (int c = 0; c < H_DIM / 32; c++) xhw[c * 32 + lane] = __float2half(xv[c]);

    float acc[E_NUM];
#pragma unroll
    for (int e = 0; e < E_NUM; e++) acc[e] = 0.f;
#pragma unroll
    for (int c = 0; c < H_DIM / 32; c++) {
        int h = c * 32 + lane;
        const float4* gwr = (const float4*)&sgw[h * 20];
#pragma unroll
        for (int q = 0; q < 4; q++) {
            float4 g4 = gwr[q];
            acc[q * 4 + 0] += xv[c] * g4.x;
            acc[q * 4 + 1] += xv[c] * g4.y;
            acc[q * 4 + 2] += xv[c] * g4.z;
            acc[q * 4 + 3] += xv[c] * g4.w;
        }
    }
#pragma unroll
    for (int e = 0; e < E_NUM; e++) {
        float v = acc[e];
        v += __shfl_down_sync(0xffffffffu, v, 16);
        v += __shfl_down_sync(0xffffffffu, v, 8);
        v += __shfl_down_sync(0xffffffffu, v, 4);
        v += __shfl_down_sync(0xffffffffu, v, 2);
        v += __shfl_down_sync(0xffffffffu, v, 1);
        acc[e] = v;
    }
    if (lane == 0) {
        float logit[E_NUM];
#pragma unroll
        for (int e = 0; e < E_NUM; e++) logit[e] = acc[e] + gb[e];
        int i0 = 0; float m0 = logit[0];
#pragma unroll
        for (int e = 1; e < E_NUM; e++) if (logit[e] > m0) { m0 = logit[e]; i0 = e; }
        int i1 = -1; float m1 = -3.0e38f;
#pragma unroll
        for (int e = 0; e < E_NUM; e++)
            if (e != i0 && logit[e] > m1) { m1 = logit[e]; i1 = e; }
        float z = expf(m1 - m0);
        float w0 = 1.f / (1.f + z);
        float w1 = z * w0;
        g_eid[t * 2 + 0] = i0; g_eid[t * 2 + 1] = i1;
        g_gw[t * 2 + 0] = w0;  g_gw[t * 2 + 1] = w1;
        atomicAdd(&g_counts[i0], 1);
        atomicAdd(&g_counts[i1], 1);
    }
}

__global__ void k_scan() {
    if (threadIdx.x == 0) {
        int off = 0;
        g_poff[0] = 0;
        for (int e = 0; e < E_NUM; e++) {
            off += (g_counts[e] + 127) & ~127;
            g_poff[e + 1] = off;
        }
    }
}

__global__ void k_scatter() {
    int t = blockIdx.x * blockDim.x + threadIdx.x;
    if (t >= T_TOK) return;
#pragma unroll
    for (int k = 0; k < 2; k++) {
        int e = g_eid[t * 2 + k];
        int pos = atomicAdd(&g_cursor[e], 1);
        int row = g_poff[e] + pos;
        g_rowtok[row] = t;
        g_tokrow[t * 2 + k] = row;
    }
}

// ---------------- grouped GEMM: all-fp16, HFMA2, k16, dbl-buffered, flush64 ----------------
template <int KDIM, int NDIM, bool GATHER, bool RELU>
__global__ __launch_bounds__(256, 2)
void k_gemm(const float* __restrict__ bias) {
    int r0 = blockIdx.x * 128;
    if (r0 >= g_poff[E_NUM]) return;
    int e = 0;
#pragma unroll
    for (int i = 1; i < E_NUM; i++) if (r0 >= g_poff[i]) e = i;

    const __half* Wb = (GATHER ? g_w1h : g_w2h) + (size_t)e * KDIM * NDIM;
    int n0 = blockIdx.y * 128;
    int tid = threadIdx.x;

    __shared__ __half As[2][16][128];
    __shared__ __half Bs[2][16][128];

    int arow = tid >> 1;
    int acol = (tid & 1) * 8;       // 8 halves = 16 B per thread
    int brow = tid >> 4;            // 0..15
    int bcol = (tid & 15) * 8;      // 8 halves = 16 B per thread

    const __half* Aptr;
    if (GATHER) {
        int tok = g_rowtok[r0 + arow];
        Aptr = (tok >= 0) ? (g_xh + (size_t)tok * KDIM + acol) : nullptr;
    } else {
        Aptr = g_h + (size_t)(r0 + arow) * KDIM + acol;
    }
    const __half* Wrow = Wb + (size_t)brow * NDIM + n0 + bcol;

    int ty = tid >> 4, tx = tid & 15;
    float accf[8][8];
#pragma unroll
    for (int i = 0; i < 8; i++)
#pragma unroll
        for (int j = 0; j < 8; j++) accf[i][j] = 0.f;

    __half2 acc2[8][4];
#pragma unroll
    for (int i = 0; i < 8; i++)
#pragma unroll
        for (int j = 0; j < 4; j++) acc2[i][j] = __float2half2_rn(0.f);

    constexpr int CHUNKS = KDIM / 16;

    // prologue: chunk 0 into buffer 0
    {
        uint4 avr = make_uint4(0u, 0u, 0u, 0u);
        if (!GATHER || Aptr) avr = *(const uint4*)(Aptr);
        const __half* hv = (const __half*)&avr;
#pragma unroll
        for (int i = 0; i < 8; i++) As[0][acol + i][arow] = hv[i];
        *(uint4*)&Bs[0][brow][bcol] = *(const uint4*)(Wrow);
    }
    __syncthreads();

    for (int c = 0; c < CHUNKS; c++) {
        const int b = c & 1;
        uint4 avr, bwr;
        const bool more = (c + 1 < CHUNKS);
        if (more) {
            avr = make_uint4(0u, 0u, 0u, 0u);
            if (!GATHER || Aptr) avr = *(const uint4*)(Aptr + (c + 1) * 16);
            bwr = *(const uint4*)(Wrow + (size_t)(c + 1) * 16 * NDIM);
        }

#pragma unroll
        for (int k = 0; k < 16; k++) {
            __half2 a2[8];
            {
                uint4 ap = *(const uint4*)&As[b][k][ty * 8];
                __half2 q0 = reinterpret_cast<__half2&>(ap.x);
                __half2 q1 = reinterpret_cast<__half2&>(ap.y);
                __half2 q2 = reinterpret_cast<__half2&>(ap.z);
                __half2 q3 = reinterpret_cast<__half2&>(ap.w);
                a2[0] = __low2half2(q0);  a2[1] = __high2half2(q0);
                a2[2] = __low2half2(q1);  a2[3] = __high2half2(q1);
                a2[4] = __low2half2(q2);  a2[5] = __high2half2(q2);
                a2[6] = __low2half2(q3);  a2[7] = __high2half2(q3);
            }
            __half2 b2[4];
            {
                uint4 bp = *(const uint4*)&Bs[b][k][tx * 8];
                b2[0] = reinterpret_cast<__half2&>(bp.x);
                b2[1] = reinterpret_cast<__half2&>(bp.y);
                b2[2] = reinterpret_cast<__half2&>(bp.z);
                b2[3] = reinterpret_cast<__half2&>(bp.w);
            }
#pragma unroll
            for (int i = 0; i < 8; i++)
#pragma unroll
                for (int j = 0; j < 4; j++)
                    acc2[i][j] = __hfma2(a2[i], b2[j], acc2[i][j]);
        }

        if ((c & 3) == 3) {   // flush fp16 window -> fp32 every 64 k-steps
#pragma unroll
            for (int i = 0; i < 8; i++)
#pragma unroll
                for (int j = 0; j < 4; j++) {
                    float2 f = __half22float2(acc2[i][j]);
                    accf[i][j * 2 + 0] += f.x;
                    accf[i][j * 2 + 1] += f.y;
                    acc2[i][j] = __float2half2_rn(0.f);
                }
        }

        if (more) {
            const int nb = 1 - b;
            const __half* hv = (const __half*)&avr;
#pragma unroll
            for (int i = 0; i < 8; i++) As[nb][acol + i][arow] = hv[i];
            *(uint4*)&Bs[nb][brow][bcol] = bwr;
            __syncthreads();
        }
    }

    float bv[8];
#pragma unroll
    for (int j = 0; j < 8; j++) bv[j] = bias[(size_t)e * NDIM + n0 + tx * 8 + j];

#pragma unroll
    for (int i = 0; i < 8; i++) {
        int r = r0 + ty * 8 + i;
        float o[8];
#pragma unroll
        for (int j = 0; j < 8; j++) {
            float v = accf[i][j] + bv[j];
            if (RELU) v = fmaxf(v, 0.f);
            o[j] = v;
        }
        if (RELU) {
            __half2 h0 = __floats2half2_rn(o[0], o[1]);
            __half2 h1 = __floats2half2_rn(o[2], o[3]);
            __half2 h2 = __floats2half2_rn(o[4], o[5]);
            __half2 h3 = __floats2half2_rn(o[6], o[7]);
            uint4 pk;
            pk.x = reinterpret_cast<uint32_t&>(h0);
            pk.y = reinterpret_cast<uint32_t&>(h1);
            pk.z = reinterpret_cast<uint32_t&>(h2);
            pk.w = reinterpret_cast<uint32_t&>(h3);
            *(uint4*)(g_h + (size_t)r * NDIM + n0 + tx * 8) = pk;
        } else {
            float* cp = g_eout + (size_t)r * NDIM + n0 + tx * 8;
            *(float4*)&cp[0] = *(float4*)&o[0];
            *(float4*)&cp[4] = *(float4*)&o[4];
        }
    }
}

// ---------------- combine + residual + LayerNorm ----------------
__global__ void k_combine_ln(const float* __restrict__ x,
                             const float* __restrict__ gamma,
                             const float* __restrict__ beta,
                             float* __restrict__ out) {
    int warp = threadIdx.x >> 5, lane = threadIdx.x & 31;
    int t = blockIdx.x * 8 + warp;
    int row0 = g_tokrow[t * 2 + 0];
    int row1 = g_tokrow[t * 2 + 1];
    float w0 = g_gw[t * 2 + 0];
    float w1 = g_gw[t * 2 + 1];
    const float* xr = x + (size_t)t * H_DIM;
    const float* o0 = g_eout + (size_t)row0 * H_DIM;
    const float* o1 = g_eout + (size_t)row1 * H_DIM;

    float v[8];
    float s = 0.f, sq = 0.f;
#pragma unroll
    for (int j = 0; j < 8; j++) {
        int h = j * 32 + lane;
        float y = xr[h] + w0 * o0[h] + w1 * o1[h];
        v[j] = y;
        s += y;
        sq += y * y;
    }
#pragma unroll
    for (int off = 16; off > 0; off >>= 1) {
        s  += __shfl_xor_sync(0xffffffffu, s, off);
        sq += __shfl_xor_sync(0xffffffffu, sq, off);
    }
    float mu = s * (1.f / H_DIM);
    float var = sq * (1.f / H_DIM) - mu * mu;
    float rs = rsqrtf(var + 1e-5f);
    float* outr = out + (size_t)t * H_DIM;
#pragma unroll
    for (int j = 0; j < 8; j++) {
        int h = j * 32 + lane;
        outr[h] = (v[j] - mu) * rs * gamma[h] + beta[h];
    }
}

// ---------------- launch ----------------
extern "C" void kernel_launch(void* const* d_in, const int* in_sizes, int n_in,
                              void* d_out, int out_size) {
    const float* x      = (const float*)d_in[0];
    const float* gate_w = (const float*)d_in[1];
    const float* gate_b = (const float*)d_in[2];
    const float* w1     = (const float*)d_in[3];
    const float* b1     = (const float*)d_in[4];
    const float* w2     = (const float*)d_in[5];
    const float* b2     = (const float*)d_in[6];
    const float* gamma  = (const float*)d_in[7];
    const float* beta   = (const float*)d_in[8];
    float* out = (float*)d_out;

    k_init<<<(ROWS_PAD + 255) / 256, 256>>>();
    k_cvt_w1<<<E_NUM * H_DIM * F_DIM / 8 / 256, 256>>>(w1);
    k_cvt_w2<<<E_NUM * F_DIM * H_DIM / 8 / 256, 256>>>(w2);
    k_gate<<<T_TOK / 8, 256>>>(x, gate_w, gate_b);
    k_scan<<<1, 32>>>();
    k_scatter<<<T_TOK / 256, 256>>>();
    k_gemm<H_DIM, F_DIM, true,  true ><<<dim3(MAXT, F_DIM / 128), 256>>>(b1);
    k_gemm<F_DIM, H_DIM, false, false><<<dim3(MAXT, H_DIM / 128), 256>>>(b2);
    k_combine_ln<<<T_TOK / 8, 256>>>(x, gamma, beta, out);
}

// round 16
// speedup vs baseline: 1.0680x; 1.0129x over previous
#include <cuda_runtime.h>
#include <cuda_fp16.h>
#include <math.h>
#include <stdint.h>

#define T_TOK   32768
#define H_DIM   256
#define F_DIM   512
#define E_NUM   16
#define ROWS_PAD 67584            // 2*T + E*128 (worst-case segment padding)
#define MAXT    (ROWS_PAD / 128)  // 528 m-tiles

// ---------------- scratch (ALL accessed via device symbols ONLY) ----------------
__device__ int    g_counts[E_NUM];
__device__ int    g_cursor[E_NUM];
__device__ int    g_poff[E_NUM + 1];
__device__ int    g_eid[T_TOK * 2];
__device__ float  g_gw[T_TOK * 2];
__device__ int    g_rowtok[ROWS_PAD];
__device__ int    g_tokrow[T_TOK * 2];
__device__ __half g_xh[(size_t)T_TOK * H_DIM];            // x (fp16)
__device__ __half g_h[(size_t)ROWS_PAD * F_DIM];          // hidden (fp16)
__device__ float  g_eout[(size_t)ROWS_PAD * H_DIM];       // expert out (fp32)
__device__ __half g_w1h[(size_t)E_NUM * H_DIM * F_DIM];   // [E][K=H][N=F] fp16
__device__ __half g_w2h[(size_t)E_NUM * F_DIM * H_DIM];   // [E][K=F][N=H] fp16

// ---------------- init ----------------
__global__ void k_init() {
    int i = blockIdx.x * blockDim.x + threadIdx.x;
    if (i < ROWS_PAD) g_rowtok[i] = -1;
    if (i < E_NUM) { g_counts[i] = 0; g_cursor[i] = 0; }
}

// ---------------- fp32 -> fp16 converters (symbol destinations) ----------------
__device__ __forceinline__ uint4 cvt8(const float* __restrict__ src, int i) {
    const float4* s = (const float4*)src + i * 2;
    float4 u0 = s[0], u1 = s[1];
    __half2 h0 = __floats2half2_rn(u0.x, u0.y);
    __half2 h1 = __floats2half2_rn(u0.z, u0.w);
    __half2 h2 = __floats2half2_rn(u1.x, u1.y);
    __half2 h3 = __floats2half2_rn(u1.z, u1.w);
    uint4 o;
    o.x = reinterpret_cast<uint32_t&>(h0);
    o.y = reinterpret_cast<uint32_t&>(h1);
    o.z = reinterpret_cast<uint32_t&>(h2);
    o.w = reinterpret_cast<uint32_t&>(h3);
    return o;
}
__global__ void k_cvt_w1(const float* __restrict__ src) {
    int i = blockIdx.x * blockDim.x + threadIdx.x;
    ((uint4*)g_w1h)[i] = cvt8(src, i);
}
__global__ void k_cvt_w2(const float* __restrict__ src) {
    int i = blockIdx.x * blockDim.x + threadIdx.x;
    ((uint4*)g_w2h)[i] = cvt8(src, i);
}

// ---------------- gating: 32 tokens/block, 4 tokens/warp; emits x fp16 ----------------
// sgw layout: [H][20] floats (16 payload + 4 pad) -> conflict-free LDS.128.
__global__ void k_gate(const float* __restrict__ x, const float* __restrict__ gw,
                       const float* __restrict__ gb) {
    __shared__ float sgw[H_DIM * 20];
    int tid = threadIdx.x;
    for (int i = tid; i < H_DIM * E_NUM; i += 256) {
        int h = i >> 4, e = i & 15;
        sgw[h * 20 + e] = gw[i];
    }
    __syncthreads();
    int warp = tid >> 5, lane = tid & 31;

#pragma unroll
    for (int tt = 0; tt < 4; tt++) {
        int t = blockIdx.x * 32 + warp * 4 + tt;
        const float* xr = x + (size_t)t * H_DIM;
        __half* xhw = g_xh + (size_t)t * H_DIM;

        float xv[8];
#pragma unroll
        for (int c = 0; c < H_DIM / 32; c++) xv[c] = xr[c * 32 + lane];
#pragma unroll
        for (int c = 0; c < H_DIM / 32; c++) xhw[c * 32 + lane] = __float2half(xv[c]);

        float acc[E_NUM];
#pragma unroll
        for (int e = 0; e < E_NUM; e++) acc[e] = 0.f;
#pragma unroll
        for (int c = 0; c < H_DIM / 32; c++) {
            int h = c * 32 + lane;
            const float4* gwr = (const float4*)&sgw[h * 20];
#pragma unroll
            for (int q = 0; q < 4; q++) {
                float4 g4 = gwr[q];
                acc[q * 4 + 0] += xv[c] * g4.x;
                acc[q * 4 + 1] += xv[c] * g4.y;
                acc[q * 4 + 2] += xv[c] * g4.z;
                acc[q * 4 + 3] += xv[c] * g4.w;
            }
        }
#pragma unroll
        for (int e = 0; e < E_NUM; e++) {
            float v = acc[e];
            v += __shfl_down_sync(0xffffffffu, v, 16);
            v += __shfl_down_sync(0xffffffffu, v, 8);
            v += __shfl_down_sync(0xffffffffu, v, 4);
            v += __shfl_down_sync(0xffffffffu, v, 2);
            v += __shfl_down_sync(0xffffffffu, v, 1);
            acc[e] = v;
        }
        if (lane == 0) {
            float logit[E_NUM];
#pragma unroll
            for (int e = 0; e < E_NUM; e++) logit[e] = acc[e] + gb[e];
            int i0 = 0; float m0 = logit[0];
#pragma unroll
            for (int e = 1; e < E_NUM; e++) if (logit[e] > m0) { m0 = logit[e]; i0 = e; }
            int i1 = -1; float m1 = -3.0e38f;
#pragma unroll
            for (int e = 0; e < E_NUM; e++)
                if (e != i0 && logit[e] > m1) { m1 = logit[e]; i1 = e; }
            float z = expf(m1 - m0);
            float w0 = 1.f / (1.f + z);
            float w1 = z * w0;
            g_eid[t * 2 + 0] = i0; g_eid[t * 2 + 1] = i1;
            g_gw[t * 2 + 0] = w0;  g_gw[t * 2 + 1] = w1;
            atomicAdd(&g_counts[i0], 1);
            atomicAdd(&g_counts[i1], 1);
        }
    }
}

__global__ void k_scan() {
    if (threadIdx.x == 0) {
        int off = 0;
        g_poff[0] = 0;
        for (int e = 0; e < E_NUM; e++) {
            off += (g_counts[e] + 127) & ~127;
            g_poff[e + 1] = off;
        }
    }
}

// ---------------- scatter: warp-aggregated atomics ----------------
__global__ void k_scatter() {
    int t = blockIdx.x * blockDim.x + threadIdx.x;
    int lane = threadIdx.x & 31;
#pragma unroll
    for (int k = 0; k < 2; k++) {
        int e = g_eid[t * 2 + k];
        unsigned mask = __match_any_sync(0xffffffffu, e);
        int leader = __ffs(mask) - 1;
        int rank = __popc(mask & ((1u << lane) - 1u));
        int base = 0;
        if (lane == leader) base = atomicAdd(&g_cursor[e], __popc(mask));
        base = __shfl_sync(0xffffffffu, base, leader);
        int row = g_poff[e] + base + rank;
        g_rowtok[row] = t;
        g_tokrow[t * 2 + k] = row;
    }
}

// ---------------- grouped GEMM: all-fp16, HFMA2, k16, dbl-buffered, flush64 ----------------
template <int KDIM, int NDIM, bool GATHER, bool RELU>
__global__ __launch_bounds__(256, 2)
void k_gemm(const float* __restrict__ bias) {
    int r0 = blockIdx.x * 128;
    if (r0 >= g_poff[E_NUM]) return;
    int e = 0;
#pragma unroll
    for (int i = 1; i < E_NUM; i++) if (r0 >= g_poff[i]) e = i;

    const __half* Wb = (GATHER ? g_w1h : g_w2h) + (size_t)e * KDIM * NDIM;
    int n0 = blockIdx.y * 128;
    int tid = threadIdx.x;

    __shared__ __half As[2][16][128];
    __shared__ __half Bs[2][16][128];

    int arow = tid >> 1;
    int acol = (tid & 1) * 8;       // 8 halves = 16 B per thread
    int brow = tid >> 4;            // 0..15
    int bcol = (tid & 15) * 8;      // 8 halves = 16 B per thread

    const __half* Aptr;
    if (GATHER) {
        int tok = g_rowtok[r0 + arow];
        Aptr = (tok >= 0) ? (g_xh + (size_t)tok * KDIM + acol) : nullptr;
    } else {
        Aptr = g_h + (size_t)(r0 + arow) * KDIM + acol;
    }
    const __half* Wrow = Wb + (size_t)brow * NDIM + n0 + bcol;

    int ty = tid >> 4, tx = tid & 15;
    float accf[8][8];
#pragma unroll
    for (int i = 0; i < 8; i++)
#pragma unroll
        for (int j = 0; j < 8; j++) accf[i][j] = 0.f;

    __half2 acc2[8][4];
#pragma unroll
    for (int i = 0; i < 8; i++)
#pragma unroll
        for (int j = 0; j < 4; j++) acc2[i][j] = __float2half2_rn(0.f);

    constexpr int CHUNKS = KDIM / 16;

    // prologue: chunk 0 into buffer 0
    {
        uint4 avr = make_uint4(0u, 0u, 0u, 0u);
        if (!GATHER || Aptr) avr = *(const uint4*)(Aptr);
        const __half* hv = (const __half*)&avr;
#pragma unroll
        for (int i = 0; i < 8; i++) As[0][acol + i][arow] = hv[i];
        *(uint4*)&Bs[0][brow][bcol] = *(const uint4*)(Wrow);
    }
    __syncthreads();

    for (int c = 0; c < CHUNKS; c++) {
        const int b = c & 1;
        uint4 avr, bwr;
        const bool more = (c + 1 < CHUNKS);
        if (more) {
            avr = make_uint4(0u, 0u, 0u, 0u);
            if (!GATHER || Aptr) avr = *(const uint4*)(Aptr + (c + 1) * 16);
            bwr = *(const uint4*)(Wrow + (size_t)(c + 1) * 16 * NDIM);
        }

#pragma unroll
        for (int k = 0; k < 16; k++) {
            __half2 a2[8];
            {
                uint4 ap = *(const uint4*)&As[b][k][ty * 8];
                __half2 q0 = reinterpret_cast<__half2&>(ap.x);
                __half2 q1 = reinterpret_cast<__half2&>(ap.y);
                __half2 q2 = reinterpret_cast<__half2&>(ap.z);
                __half2 q3 = reinterpret_cast<__half2&>(ap.w);
                a2[0] = __low2half2(q0);  a2[1] = __high2half2(q0);
                a2[2] = __low2half2(q1);  a2[3] = __high2half2(q1);
                a2[4] = __low2half2(q2);  a2[5] = __high2half2(q2);
                a2[6] = __low2half2(q3);  a2[7] = __high2half2(q3);
            }
            __half2 b2[4];
            {
                uint4 bp = *(const uint4*)&Bs[b][k][tx * 8];
                b2[0] = reinterpret_cast<__half2&>(bp.x);
                b2[1] = reinterpret_cast<__half2&>(bp.y);
                b2[2] = reinterpret_cast<__half2&>(bp.z);
                b2[3] = reinterpret_cast<__half2&>(bp.w);
            }
#pragma unroll
            for (int i = 0; i < 8; i++)
#pragma unroll
                for (int j = 0; j < 4; j++)
                    acc2[i][j] = __hfma2(a2[i], b2[j], acc2[i][j]);
        }

        if ((c & 3) == 3) {   // flush fp16 window -> fp32 every 64 k-steps
#pragma unroll
            for (int i = 0; i < 8; i++)
#pragma unroll
                for (int j = 0; j < 4; j++) {
                    float2 f = __half22float2(acc2[i][j]);
                    accf[i][j * 2 + 0] += f.x;
                    accf[i][j * 2 + 1] += f.y;
                    acc2[i][j] = __float2half2_rn(0.f);
                }
        }

        if (more) {
            const int nb = 1 - b;
            const __half* hv = (const __half*)&avr;
#pragma unroll
            for (int i = 0; i < 8; i++) As[nb][acol + i][arow] = hv[i];
            *(uint4*)&Bs[nb][brow][bcol] = bwr;
            __syncthreads();
        }
    }

    float bv[8];
#pragma unroll
    for (int j = 0; j < 8; j++) bv[j] = bias[(size_t)e * NDIM + n0 + tx * 8 + j];

#pragma unroll
    for (int i = 0; i < 8; i++) {
        int r = r0 + ty * 8 + i;
        float o[8];
#pragma unroll
        for (int j = 0; j < 8; j++) {
            float v = accf[i][j] + bv[j];
            if (RELU) v = fmaxf(v, 0.f);
            o[j] = v;
        }
        if (RELU) {
            __half2 h0 = __floats2half2_rn(o[0], o[1]);
            __half2 h1 = __floats2half2_rn(o[2], o[3]);
            __half2 h2 = __floats2half2_rn(o[4], o[5]);
            __half2 h3 = __floats2half2_rn(o[6], o[7]);
            uint4 pk;
            pk.x = reinterpret_cast<uint32_t&>(h0);
            pk.y = reinterpret_cast<uint32_t&>(h1);
            pk.z = reinterpret_cast<uint32_t&>(h2);
            pk.w = reinterpret_cast<uint32_t&>(h3);
            *(uint4*)(g_h + (size_t)r * NDIM + n0 + tx * 8) = pk;
        } else {
            float* cp = g_eout + (size_t)r * NDIM + n0 + tx * 8;
            *(float4*)&cp[0] = *(float4*)&o[0];
            *(float4*)&cp[4] = *(float4*)&o[4];
        }
    }
}

// ---------------- combine + residual + LayerNorm ----------------
__global__ void k_combine_ln(const float* __restrict__ x,
                             const float* __restrict__ gamma,
                             const float* __restrict__ beta,
                             float* __restrict__ out) {
    int warp = threadIdx.x >> 5, lane = threadIdx.x & 31;
    int t = blockIdx.x * 8 + warp;
    int row0 = g_tokrow[t * 2 + 0];
    int row1 = g_tokrow[t * 2 + 1];
    float w0 = g_gw[t * 2 + 0];
    float w1 = g_gw[t * 2 + 1];
    const float* xr = x + (size_t)t * H_DIM;
    const float* o0 = g_eout + (size_t)row0 * H_DIM;
    const float* o1 = g_eout + (size_t)row1 * H_DIM;

    float v[8];
    float s = 0.f, sq = 0.f;
#pragma unroll
    for (int j = 0; j < 8; j++) {
        int h = j * 32 + lane;
        float y = xr[h] + w0 * o0[h] + w1 * o1[h];
        v[j] = y;
        s += y;
        sq += y * y;
    }
#pragma unroll
    for (int off = 16; off > 0; off >>= 1) {
        s  += __shfl_xor_sync(0xffffffffu, s, off);
        sq += __shfl_xor_sync(0xffffffffu, sq, off);
    }
    float mu = s * (1.f / H_DIM);
    float var = sq * (1.f / H_DIM) - mu * mu;
    float rs = rsqrtf(var + 1e-5f);
    float* outr = out + (size_t)t * H_DIM;
#pragma unroll
    for (int j = 0; j < 8; j++) {
        int h = j * 32 + lane;
        outr[h] = (v[j] - mu) * rs * gamma[h] + beta[h];
    }
}

// ---------------- launch ----------------
extern "C" void kernel_launch(void* const* d_in, const int* in_sizes, int n_in,
                              void* d_out, int out_size) {
    const float* x      = (const float*)d_in[0];
    const float* gate_w = (const float*)d_in[1];
    const float* gate_b = (const float*)d_in[2];
    const float* w1     = (const float*)d_in[3];
    const float* b1     = (const float*)d_in[4];
    const float* w2     = (const float*)d_in[5];
    const float* b2     = (const float*)d_in[6];
    const float* gamma  = (const float*)d_in[7];
    const float* beta   = (const float*)d_in[8];
    float* out = (float*)d_out;

    k_init<<<(ROWS_PAD + 255) / 256, 256>>>();
    k_cvt_w1<<<E_NUM * H_DIM * F_DIM / 8 / 256, 256>>>(w1);
    k_cvt_w2<<<E_NUM * F_DIM * H_DIM / 8 / 256, 256>>>(w2);
    k_gate<<<T_TOK / 32, 256>>>(x, gate_w, gate_b);
    k_scan<<<1, 32>>>();
    k_scatter<<<T_TOK / 256, 256>>>();
    k_gemm<H_DIM, F_DIM, true,  true ><<<dim3(MAXT, F_DIM / 128), 256>>>(b1);
    k_gemm<F_DIM, H_DIM, false, false><<<dim3(MAXT, H_DIM / 128), 256>>>(b2);
    k_combine_ln<<<T_TOK / 8, 256>>>(x, gamma, beta, out);
}